// round 1
// baseline (speedup 1.0000x reference)
#include <cuda_runtime.h>
#include <cuda_bf16.h>
#include <math.h>

// Problem constants
constexpr int Bc  = 8;
constexpr int Lc  = 4096;
constexpr int NH  = 16;
constexpr int HD  = 64;
constexpr int HID = 1024;           // NH*HD == NHID == 1024
constexpr int MTOK = Bc * Lc;       // 32768

// Scratch (device globals: no allocation allowed)
__device__ float g_q  [(size_t)MTOK * HID];
__device__ float g_k  [(size_t)MTOK * HID];
__device__ float g_att[(size_t)MTOK * HID];
__device__ float g_ak [Bc * HID];
__device__ float g_av [Bc * HID];

// ---------------------------------------------------------------------------
// SGEMM: C[M x 1024] = A[M x 1024] @ W[1024 x 1024] + bias, all row-major fp32
// 128x128 tile, BK=16, 256 threads, 8x8 per-thread, double-buffered smem.
// M, N, K all multiples of tile sizes -> no bounds checks.
// ---------------------------------------------------------------------------
__global__ __launch_bounds__(256)
void sgemm_bias(const float* __restrict__ A,
                const float* __restrict__ W,
                const float* __restrict__ bias,
                float* __restrict__ C)
{
    constexpr int K = 1024, N = 1024;
    constexpr int BM = 128, BN = 128, BK = 16;

    __shared__ float As[2][BK][BM];
    __shared__ float Bs[2][BK][BN];

    const int tid = threadIdx.x;
    const int tx  = tid & 15;       // col group (0..15)
    const int ty  = tid >> 4;       // row group (0..15)
    const int row0 = blockIdx.y * BM;
    const int col0 = blockIdx.x * BN;

    // A tile load mapping: 128 rows x 16 cols, 2 float4 per thread
    const int arow = tid >> 2;            // 0..63 (and +64)
    const int acol = (tid & 3) * 4;       // 0,4,8,12
    // B tile load mapping: 16 rows x 128 cols, 2 float4 per thread
    const int brow = tid >> 5;            // 0..7 (and +8)
    const int bcol = (tid & 31) * 4;      // 0..124

    const float* Ab = A + (size_t)row0 * K;
    const float* Wb = W + col0;

    float acc[8][8];
    #pragma unroll
    for (int i = 0; i < 8; ++i)
        #pragma unroll
        for (int j = 0; j < 8; ++j) acc[i][j] = 0.f;

    float4 pa0, pa1, pb0, pb1;   // prefetch regs

    // gmem -> regs for k-tile kt
    auto loadG = [&](int kt) {
        pa0 = *(const float4*)(Ab + (size_t)arow        * K + kt + acol);
        pa1 = *(const float4*)(Ab + (size_t)(arow + 64) * K + kt + acol);
        pb0 = *(const float4*)(Wb + (size_t)(kt + brow    ) * N + bcol);
        pb1 = *(const float4*)(Wb + (size_t)(kt + brow + 8) * N + bcol);
    };
    // regs -> smem buffer
    auto storeS = [&](int buf) {
        As[buf][acol + 0][arow]      = pa0.x;
        As[buf][acol + 1][arow]      = pa0.y;
        As[buf][acol + 2][arow]      = pa0.z;
        As[buf][acol + 3][arow]      = pa0.w;
        As[buf][acol + 0][arow + 64] = pa1.x;
        As[buf][acol + 1][arow + 64] = pa1.y;
        As[buf][acol + 2][arow + 64] = pa1.z;
        As[buf][acol + 3][arow + 64] = pa1.w;
        *(float4*)&Bs[buf][brow    ][bcol] = pb0;
        *(float4*)&Bs[buf][brow + 8][bcol] = pb1;
    };
    auto compute = [&](int buf) {
        #pragma unroll
        for (int kk = 0; kk < BK; ++kk) {
            float a[8], b[8];
            *(float4*)(a    ) = *(const float4*)&As[buf][kk][ty * 8    ];
            *(float4*)(a + 4) = *(const float4*)&As[buf][kk][ty * 8 + 4];
            *(float4*)(b    ) = *(const float4*)&Bs[buf][kk][tx * 8    ];
            *(float4*)(b + 4) = *(const float4*)&Bs[buf][kk][tx * 8 + 4];
            #pragma unroll
            for (int i = 0; i < 8; ++i)
                #pragma unroll
                for (int j = 0; j < 8; ++j)
                    acc[i][j] = fmaf(a[i], b[j], acc[i][j]);
        }
    };

    int buf = 0;
    loadG(0);
    storeS(0);
    __syncthreads();
    for (int kt = BK; kt < K; kt += BK) {
        loadG(kt);            // LDGs in flight while computing
        compute(buf);
        storeS(buf ^ 1);
        __syncthreads();
        buf ^= 1;
    }
    compute(buf);

    // epilogue: + bias, store
    float bs[8];
    #pragma unroll
    for (int j = 0; j < 8; ++j) bs[j] = bias[col0 + tx * 8 + j];
    #pragma unroll
    for (int i = 0; i < 8; ++i) {
        float* crow = C + (size_t)(row0 + ty * 8 + i) * N + col0 + tx * 8;
        float4 v0, v1;
        v0.x = acc[i][0] + bs[0]; v0.y = acc[i][1] + bs[1];
        v0.z = acc[i][2] + bs[2]; v0.w = acc[i][3] + bs[3];
        v1.x = acc[i][4] + bs[4]; v1.y = acc[i][5] + bs[5];
        v1.z = acc[i][6] + bs[6]; v1.w = acc[i][7] + bs[7];
        *(float4*)(crow    ) = v0;
        *(float4*)(crow + 4) = v1;
    }
}

// ---------------------------------------------------------------------------
// Tiny projections: ak = ax@WK + bK, av = ax@WV + bV   (8 x 1024 each)
// 64 blocks x 256 threads; one output element per thread.
// ---------------------------------------------------------------------------
__global__ __launch_bounds__(256)
void proj_small(const float* __restrict__ ax,
                const float* __restrict__ WK, const float* __restrict__ WKb,
                const float* __restrict__ WV, const float* __restrict__ WVb)
{
    __shared__ float xs[HID];
    const int sel = blockIdx.x >> 5;            // 0: ak, 1: av
    const int bb  = (blockIdx.x >> 2) & 7;      // batch
    const int n   = ((blockIdx.x & 3) << 8) + threadIdx.x;

    for (int i = threadIdx.x; i < HID; i += 256) xs[i] = ax[bb * HID + i];
    __syncthreads();

    const float* W    = sel ? WV  : WK;
    const float* bias = sel ? WVb : WKb;
    float acc = 0.f;
    #pragma unroll 8
    for (int kk = 0; kk < HID; ++kk)
        acc = fmaf(xs[kk], W[(size_t)kk * HID + n], acc);

    float* o = sel ? g_av : g_ak;
    o[bb * HID + n] = acc + bias[n];
}

// ---------------------------------------------------------------------------
// Attention: 4 slots = [global(ak/av), k[l-1], k[l], k[l+1]] per (b,l,h).
// Local V slots == K slots (faithful to reference's pad_v bug).
// One warp per (b,l,h); lane owns 2 of the 64 head dims.
// ---------------------------------------------------------------------------
__global__ __launch_bounds__(256)
void attn_kernel(const float* __restrict__ q, const float* __restrict__ k,
                 float* __restrict__ att)
{
    const int w    = (blockIdx.x * blockDim.x + threadIdx.x) >> 5;
    const int lane = threadIdx.x & 31;
    const int h = w & 15;
    const int l = (w >> 4) & (Lc - 1);
    const int b = w >> 16;

    const size_t rowbase = ((size_t)(b * Lc + l)) * HID + h * HD + lane * 2;
    const size_t gbase   = (size_t)b * HID + h * HD + lane * 2;

    float2 qv = *(const float2*)(q + rowbase);
    float2 k0 = *(const float2*)(g_ak + gbase);
    float2 v0 = *(const float2*)(g_av + gbase);
    float2 k1 = make_float2(0.f, 0.f);
    float2 k3 = make_float2(0.f, 0.f);
    if (l > 0)      k1 = *(const float2*)(k + rowbase - HID);
    float2 k2 = *(const float2*)(k + rowbase);
    if (l < Lc - 1) k3 = *(const float2*)(k + rowbase + HID);

    float p0 = qv.x * k0.x + qv.y * k0.y;
    float p1 = qv.x * k1.x + qv.y * k1.y;
    float p2 = qv.x * k2.x + qv.y * k2.y;
    float p3 = qv.x * k3.x + qv.y * k3.y;
    #pragma unroll
    for (int o = 16; o; o >>= 1) {
        p0 += __shfl_xor_sync(0xFFFFFFFFu, p0, o);
        p1 += __shfl_xor_sync(0xFFFFFFFFu, p1, o);
        p2 += __shfl_xor_sync(0xFFFFFFFFu, p2, o);
        p3 += __shfl_xor_sync(0xFFFFFFFFu, p3, o);
    }
    const float scale = 0.125f;   // 1/sqrt(64)
    float s0 = p0 * scale, s1 = p1 * scale, s2 = p2 * scale, s3 = p3 * scale;
    float m = fmaxf(fmaxf(s0, s1), fmaxf(s2, s3));
    float e0 = __expf(s0 - m), e1 = __expf(s1 - m),
          e2 = __expf(s2 - m), e3 = __expf(s3 - m);
    float inv = 1.f / (e0 + e1 + e2 + e3);
    float a0 = e0 * inv, a1 = e1 * inv, a2 = e2 * inv, a3 = e3 * inv;

    float2 o;
    o.x = a0 * v0.x + a1 * k1.x + a2 * k2.x + a3 * k3.x;
    o.y = a0 * v0.y + a1 * k1.y + a2 * k2.y + a3 * k3.y;
    *(float2*)(att + rowbase) = o;
}

// ---------------------------------------------------------------------------
extern "C" void kernel_launch(void* const* d_in, const int* in_sizes, int n_in,
                              void* d_out, int out_size)
{
    const float* x    = (const float*)d_in[0];
    const float* ax   = (const float*)d_in[1];
    const float* WQ_w = (const float*)d_in[2];
    const float* WQ_b = (const float*)d_in[3];
    const float* WK_w = (const float*)d_in[4];
    const float* WK_b = (const float*)d_in[5];
    const float* WV_w = (const float*)d_in[6];
    const float* WV_b = (const float*)d_in[7];
    const float* WO_w = (const float*)d_in[8];
    const float* WO_b = (const float*)d_in[9];
    float* out = (float*)d_out;

    float *qp, *kp, *attp;
    cudaGetSymbolAddress((void**)&qp,   g_q);
    cudaGetSymbolAddress((void**)&kp,   g_k);
    cudaGetSymbolAddress((void**)&attp, g_att);

    dim3 gg(HID / 128, MTOK / 128);   // (8, 256)
    sgemm_bias<<<gg, 256>>>(x, WQ_w, WQ_b, qp);
    sgemm_bias<<<gg, 256>>>(x, WK_w, WK_b, kp);
    proj_small<<<64, 256>>>(ax, WK_w, WK_b, WV_w, WV_b);

    // 8*4096*16 warps, 8 warps/block
    attn_kernel<<<(Bc * Lc * NH) / 8, 256>>>(qp, kp, attp);

    sgemm_bias<<<gg, 256>>>(attp, WO_w, WO_b, out);
}

// round 4
// speedup vs baseline: 2.6887x; 2.6887x over previous
#include <cuda_runtime.h>
#include <cuda_fp16.h>

// ---------------------------------------------------------------------------
// Problem constants
// ---------------------------------------------------------------------------
constexpr int Bc  = 8;
constexpr int Lc  = 4096;
constexpr int NH  = 16;
constexpr int HD  = 64;
constexpr int HID = 1024;
constexpr int MTOK = Bc * Lc;       // 32768
constexpr int Kdim = 1024;

// GEMM tiling
constexpr int BM = 128, BN = 128, BK = 64;
constexpr int NC = Kdim / BK;       // 16 k-chunks
// smem stage layout (bytes): Ahi 16K | Alo 16K | Bhi 16K | Blo 16K
constexpr int ST_AHI = 0;
constexpr int ST_ALO = 16384;
constexpr int ST_BHI = 32768;
constexpr int ST_BLO = 49152;
constexpr int STAGE_BYTES = 65536;
constexpr int SMEM_REQ = 2 * STAGE_BYTES + 1024;

// ---------------------------------------------------------------------------
// Scratch (device globals: no allocation allowed)
// ---------------------------------------------------------------------------
__device__ float g_q  [(size_t)MTOK * HID];
__device__ float g_k  [(size_t)MTOK * HID];
__device__ float g_ak [Bc * HID];
__device__ float g_av [Bc * HID];
__device__ __half g_xhi [(size_t)MTOK * HID];
__device__ __half g_xlo [(size_t)MTOK * HID];
__device__ __half g_ahi [(size_t)MTOK * HID];   // attention out hi
__device__ __half g_alo [(size_t)MTOK * HID];   // attention out lo
__device__ __half g_wqT_hi[Kdim * HID], g_wqT_lo[Kdim * HID];
__device__ __half g_wkT_hi[Kdim * HID], g_wkT_lo[Kdim * HID];
__device__ __half g_woT_hi[Kdim * HID], g_woT_lo[Kdim * HID];

// ---------------------------------------------------------------------------
// helpers
// ---------------------------------------------------------------------------
__device__ __forceinline__ unsigned smem_u32(const void* p) {
    unsigned a;
    asm("{ .reg .u64 t; cvta.to.shared.u64 t, %1; cvt.u32.u64 %0, t; }"
        : "=r"(a) : "l"(p));
    return a;
}
__device__ __forceinline__ void cp16(unsigned saddr, const void* g) {
    asm volatile("cp.async.cg.shared.global [%0], [%1], 16;\n"
                 :: "r"(saddr), "l"(g));
}
#define CP_COMMIT() asm volatile("cp.async.commit_group;\n" ::: "memory")
#define CP_WAIT1()  asm volatile("cp.async.wait_group 1;\n" ::: "memory")
#define CP_WAIT0()  asm volatile("cp.async.wait_group 0;\n" ::: "memory")

__device__ __forceinline__ void ldsm4(unsigned& r0, unsigned& r1,
                                      unsigned& r2, unsigned& r3, unsigned a) {
    asm volatile("ldmatrix.sync.aligned.m8n8.x4.shared.b16 {%0,%1,%2,%3}, [%4];"
                 : "=r"(r0), "=r"(r1), "=r"(r2), "=r"(r3) : "r"(a));
}
__device__ __forceinline__ void mma16816(float* c, const unsigned* a,
                                         const unsigned* b) {
    asm volatile(
        "mma.sync.aligned.m16n8k16.row.col.f32.f16.f16.f32 "
        "{%0,%1,%2,%3}, {%4,%5,%6,%7}, {%8,%9}, {%0,%1,%2,%3};"
        : "+f"(c[0]), "+f"(c[1]), "+f"(c[2]), "+f"(c[3])
        : "r"(a[0]), "r"(a[1]), "r"(a[2]), "r"(a[3]), "r"(b[0]), "r"(b[1]));
}

// ---------------------------------------------------------------------------
// Split-fp16 HMMA GEMM: C[M,1024] = (Ahi+Alo) @ (Bhi+Blo)^T + bias
// B operands given transposed: [N,K] K-major.
// CTA 128x128, BK=64, 8 warps (2x4), warp tile 64x32, 2-stage cp.async.
// ---------------------------------------------------------------------------
__global__ __launch_bounds__(256, 1)
void gemm_mma(const __half* __restrict__ Ahi, const __half* __restrict__ Alo,
              const __half* __restrict__ Bhi, const __half* __restrict__ Blo,
              const float* __restrict__ bias, float* __restrict__ C)
{
    extern __shared__ char smem_raw[];
    const unsigned sbase = (smem_u32(smem_raw) + 1023u) & ~1023u;
    const int tid  = threadIdx.x;
    const int wid  = tid >> 5;
    const int lane = tid & 31;
    const int row0 = blockIdx.y * BM;
    const int col0 = blockIdx.x * BN;

    // ---- async tile loader: 4 arrays x 1024 float4-equiv (16B) each ----
    auto load_chunk = [&](int c, int s) {
        const unsigned sa = sbase + s * STAGE_BYTES;
        const int kt = c * BK;
        #pragma unroll
        for (int i = 0; i < 4; ++i) {
            int v = tid + i * 256;          // 0..1023
            int r = v >> 3, u = v & 7;      // row 0..127, 16B unit 0..7
            unsigned bo = (unsigned)(r * 128 + u * 16);
            unsigned so = bo ^ ((bo >> 3) & 0x70);   // SW128
            size_t goA = (size_t)(row0 + r) * Kdim + kt + u * 8;
            size_t goB = (size_t)(col0 + r) * Kdim + kt + u * 8;
            cp16(sa + ST_AHI + so, Ahi + goA);
            cp16(sa + ST_ALO + so, Alo + goA);
            cp16(sa + ST_BHI + so, Bhi + goB);
            cp16(sa + ST_BLO + so, Blo + goB);
        }
        CP_COMMIT();
    };

    // ---- per-lane ldmatrix address components ----
    const int mrow0 = (wid >> 2) * 64;      // warp M offset
    const int nrow0 = (wid & 3) * 32;       // warp N offset
    const unsigned rtA  = (lane & 7) + ((lane >> 3) & 1) * 8;   // A row term
    const unsigned s16A = ((lane >> 4) & 1) * 16;               // A col byte term
    const unsigned rtB  = (lane & 7) + ((lane >> 4) & 1) * 8;   // B row term
    const unsigned s16B = ((lane >> 3) & 1) * 16;               // B col byte term
    const unsigned xorv = (lane & 7) * 16;                      // SW128 xor

    float acc[4][4][4];
    #pragma unroll
    for (int mi = 0; mi < 4; ++mi)
        #pragma unroll
        for (int ni = 0; ni < 4; ++ni)
            #pragma unroll
            for (int r = 0; r < 4; ++r) acc[mi][ni][r] = 0.f;

    load_chunk(0, 0);
    load_chunk(1, 1);

    for (int c = 0; c < NC; ++c) {
        const int s = c & 1;
        CP_WAIT1();
        __syncthreads();

        const unsigned sa   = sbase + s * STAGE_BYTES;
        const unsigned pAhi = sa + ST_AHI + (mrow0 + rtA) * 128;
        const unsigned pAlo = sa + ST_ALO + (mrow0 + rtA) * 128;
        const unsigned pBhi = sa + ST_BHI + (nrow0 + rtB) * 128;
        const unsigned pBlo = sa + ST_BLO + (nrow0 + rtB) * 128;

        #pragma unroll
        for (int kk = 0; kk < 4; ++kk) {
            const unsigned colA = ((unsigned)(kk * 32) + s16A) ^ xorv;
            const unsigned colB = ((unsigned)(kk * 32) + s16B) ^ xorv;
            unsigned ah[4][4], al[4][4], bh[2][4], bl[2][4];
            #pragma unroll
            for (int mi = 0; mi < 4; ++mi) {
                ldsm4(ah[mi][0], ah[mi][1], ah[mi][2], ah[mi][3],
                      pAhi + mi * 2048 + colA);
                ldsm4(al[mi][0], al[mi][1], al[mi][2], al[mi][3],
                      pAlo + mi * 2048 + colA);
            }
            #pragma unroll
            for (int nb = 0; nb < 2; ++nb) {
                ldsm4(bh[nb][0], bh[nb][1], bh[nb][2], bh[nb][3],
                      pBhi + nb * 2048 + colB);
                ldsm4(bl[nb][0], bl[nb][1], bl[nb][2], bl[nb][3],
                      pBlo + nb * 2048 + colB);
            }
            #pragma unroll
            for (int mi = 0; mi < 4; ++mi)
                #pragma unroll
                for (int ni = 0; ni < 4; ++ni) {
                    const unsigned* bhp = &bh[ni >> 1][(ni & 1) * 2];
                    const unsigned* blp = &bl[ni >> 1][(ni & 1) * 2];
                    mma16816(acc[mi][ni], ah[mi], bhp);   // hi*hi
                    mma16816(acc[mi][ni], ah[mi], blp);   // hi*lo
                    mma16816(acc[mi][ni], al[mi], bhp);   // lo*hi
                }
        }

        __syncthreads();                 // all warps done with stage s
        if (c + 2 < NC) load_chunk(c + 2, s);
    }
    CP_WAIT0();

    // ---- epilogue: acc + bias -> C ----
    #pragma unroll
    for (int ni = 0; ni < 4; ++ni) {
        const int cc = col0 + nrow0 + ni * 8 + (lane & 3) * 2;
        const float b0 = bias[cc], b1 = bias[cc + 1];
        #pragma unroll
        for (int mi = 0; mi < 4; ++mi) {
            const int r = row0 + mrow0 + mi * 16 + (lane >> 2);
            float2 v0 = make_float2(acc[mi][ni][0] + b0, acc[mi][ni][1] + b1);
            float2 v1 = make_float2(acc[mi][ni][2] + b0, acc[mi][ni][3] + b1);
            *(float2*)(C + (size_t)r * HID + cc)       = v0;
            *(float2*)(C + (size_t)(r + 8) * HID + cc) = v1;
        }
    }
}

// ---------------------------------------------------------------------------
// fp32 -> (hi, lo) fp16 split, vectorized
// ---------------------------------------------------------------------------
__global__ __launch_bounds__(256)
void split_f32(const float* __restrict__ in, __half* __restrict__ hi,
               __half* __restrict__ lo, int n4)
{
    int i = blockIdx.x * blockDim.x + threadIdx.x;
    if (i >= n4) return;
    float4 v = ((const float4*)in)[i];
    __half h0 = __float2half_rn(v.x), h1 = __float2half_rn(v.y);
    __half h2 = __float2half_rn(v.z), h3 = __float2half_rn(v.w);
    __half l0 = __float2half_rn(v.x - __half2float(h0));
    __half l1 = __float2half_rn(v.y - __half2float(h1));
    __half l2 = __float2half_rn(v.z - __half2float(h2));
    __half l3 = __float2half_rn(v.w - __half2float(h3));
    __half2* hp = (__half2*)(hi + (size_t)i * 4);
    __half2* lp = (__half2*)(lo + (size_t)i * 4);
    hp[0] = __half2(h0, h1); hp[1] = __half2(h2, h3);
    lp[0] = __half2(l0, l1); lp[1] = __half2(l2, l3);
}

// ---------------------------------------------------------------------------
// W [K,N] fp32 -> W^T hi/lo fp16 [N,K]
// ---------------------------------------------------------------------------
__global__ __launch_bounds__(256)
void transpose_split(const float* __restrict__ W,
                     __half* __restrict__ ThT, __half* __restrict__ TlT)
{
    __shared__ float t[32][33];
    const int tx = threadIdx.x, ty = threadIdx.y;   // (32, 8)
    const int n0 = blockIdx.x * 32, k0 = blockIdx.y * 32;
    #pragma unroll
    for (int i = 0; i < 32; i += 8)
        t[ty + i][tx] = W[(size_t)(k0 + ty + i) * HID + n0 + tx];
    __syncthreads();
    #pragma unroll
    for (int i = 0; i < 32; i += 8) {
        float v = t[tx][ty + i];
        __half h = __float2half_rn(v);
        __half l = __float2half_rn(v - __half2float(h));
        ThT[(size_t)(n0 + ty + i) * Kdim + k0 + tx] = h;
        TlT[(size_t)(n0 + ty + i) * Kdim + k0 + tx] = l;
    }
}

// ---------------------------------------------------------------------------
// Tiny projections: ak = ax@WK + bK, av = ax@WV + bV (fp32, 8x1024 each)
// ---------------------------------------------------------------------------
__global__ __launch_bounds__(256)
void proj_small(const float* __restrict__ ax,
                const float* __restrict__ WK, const float* __restrict__ WKb,
                const float* __restrict__ WV, const float* __restrict__ WVb)
{
    __shared__ float xs[HID];
    const int sel = blockIdx.x >> 5;
    const int bb  = (blockIdx.x >> 2) & 7;
    const int n   = ((blockIdx.x & 3) << 8) + threadIdx.x;
    for (int i = threadIdx.x; i < HID; i += 256) xs[i] = ax[bb * HID + i];
    __syncthreads();
    const float* W    = sel ? WV  : WK;
    const float* bias = sel ? WVb : WKb;
    float acc = 0.f;
    #pragma unroll 8
    for (int kk = 0; kk < HID; ++kk)
        acc = fmaf(xs[kk], W[(size_t)kk * HID + n], acc);
    float* o = sel ? g_av : g_ak;
    o[bb * HID + n] = acc + bias[n];
}

// ---------------------------------------------------------------------------
// Attention (fp32 compute), emits fp16 hi/lo split directly for O-GEMM.
// ---------------------------------------------------------------------------
__global__ __launch_bounds__(256)
void attn_kernel(const float* __restrict__ q, const float* __restrict__ k,
                 __half* __restrict__ ahi, __half* __restrict__ alo)
{
    const int w    = (blockIdx.x * blockDim.x + threadIdx.x) >> 5;
    const int lane = threadIdx.x & 31;
    const int h = w & 15;
    const int l = (w >> 4) & (Lc - 1);
    const int b = w >> 16;

    const size_t rowbase = ((size_t)(b * Lc + l)) * HID + h * HD + lane * 2;
    const size_t gbase   = (size_t)b * HID + h * HD + lane * 2;

    float2 qv = *(const float2*)(q + rowbase);
    float2 k0 = *(const float2*)(g_ak + gbase);
    float2 v0 = *(const float2*)(g_av + gbase);
    float2 k1 = make_float2(0.f, 0.f);
    float2 k3 = make_float2(0.f, 0.f);
    if (l > 0)      k1 = *(const float2*)(k + rowbase - HID);
    float2 k2 = *(const float2*)(k + rowbase);
    if (l < Lc - 1) k3 = *(const float2*)(k + rowbase + HID);

    float p0 = qv.x * k0.x + qv.y * k0.y;
    float p1 = qv.x * k1.x + qv.y * k1.y;
    float p2 = qv.x * k2.x + qv.y * k2.y;
    float p3 = qv.x * k3.x + qv.y * k3.y;
    #pragma unroll
    for (int o = 16; o; o >>= 1) {
        p0 += __shfl_xor_sync(0xFFFFFFFFu, p0, o);
        p1 += __shfl_xor_sync(0xFFFFFFFFu, p1, o);
        p2 += __shfl_xor_sync(0xFFFFFFFFu, p2, o);
        p3 += __shfl_xor_sync(0xFFFFFFFFu, p3, o);
    }
    const float scale = 0.125f;
    float s0 = p0 * scale, s1 = p1 * scale, s2 = p2 * scale, s3 = p3 * scale;
    float m = fmaxf(fmaxf(s0, s1), fmaxf(s2, s3));
    float e0 = __expf(s0 - m), e1 = __expf(s1 - m),
          e2 = __expf(s2 - m), e3 = __expf(s3 - m);
    float inv = 1.f / (e0 + e1 + e2 + e3);
    float a0 = e0 * inv, a1 = e1 * inv, a2 = e2 * inv, a3 = e3 * inv;

    float ox = a0 * v0.x + a1 * k1.x + a2 * k2.x + a3 * k3.x;
    float oy = a0 * v0.y + a1 * k1.y + a2 * k2.y + a3 * k3.y;

    __half hx = __float2half_rn(ox), hy = __float2half_rn(oy);
    __half lx = __float2half_rn(ox - __half2float(hx));
    __half ly = __float2half_rn(oy - __half2float(hy));
    *(__half2*)(ahi + rowbase) = __half2(hx, hy);
    *(__half2*)(alo + rowbase) = __half2(lx, ly);
}

// ---------------------------------------------------------------------------
extern "C" void kernel_launch(void* const* d_in, const int* in_sizes, int n_in,
                              void* d_out, int out_size)
{
    const float* x    = (const float*)d_in[0];
    const float* ax   = (const float*)d_in[1];
    const float* WQ_w = (const float*)d_in[2];
    const float* WQ_b = (const float*)d_in[3];
    const float* WK_w = (const float*)d_in[4];
    const float* WK_b = (const float*)d_in[5];
    const float* WV_w = (const float*)d_in[6];
    const float* WV_b = (const float*)d_in[7];
    const float* WO_w = (const float*)d_in[8];
    const float* WO_b = (const float*)d_in[9];
    float* out = (float*)d_out;

    float *qp, *kp;
    __half *xhi, *xlo, *ahi, *alo;
    __half *wqh, *wql, *wkh, *wkl, *woh, *wol;
    cudaGetSymbolAddress((void**)&qp,  g_q);
    cudaGetSymbolAddress((void**)&kp,  g_k);
    cudaGetSymbolAddress((void**)&xhi, g_xhi);
    cudaGetSymbolAddress((void**)&xlo, g_xlo);
    cudaGetSymbolAddress((void**)&ahi, g_ahi);
    cudaGetSymbolAddress((void**)&alo, g_alo);
    cudaGetSymbolAddress((void**)&wqh, g_wqT_hi);
    cudaGetSymbolAddress((void**)&wql, g_wqT_lo);
    cudaGetSymbolAddress((void**)&wkh, g_wkT_hi);
    cudaGetSymbolAddress((void**)&wkl, g_wkT_lo);
    cudaGetSymbolAddress((void**)&woh, g_woT_hi);
    cudaGetSymbolAddress((void**)&wol, g_woT_lo);

    cudaFuncSetAttribute(gemm_mma,
                         cudaFuncAttributeMaxDynamicSharedMemorySize, SMEM_REQ);

    // splits
    const int n4 = MTOK * HID / 4;
    split_f32<<<n4 / 256, 256>>>(x, xhi, xlo, n4);
    dim3 tb(32, 8), tg(32, 32);
    transpose_split<<<tg, tb>>>(WQ_w, wqh, wql);
    transpose_split<<<tg, tb>>>(WK_w, wkh, wkl);
    transpose_split<<<tg, tb>>>(WO_w, woh, wol);
    proj_small<<<64, 256>>>(ax, WK_w, WK_b, WV_w, WV_b);

    // Q, K projections on tensor cores
    dim3 gg(HID / BN, MTOK / BM);   // (8, 256)
    gemm_mma<<<gg, 256, SMEM_REQ>>>(xhi, xlo, wqh, wql, WQ_b, qp);
    gemm_mma<<<gg, 256, SMEM_REQ>>>(xhi, xlo, wkh, wkl, WK_b, kp);

    // attention -> fp16 split output
    attn_kernel<<<(Bc * Lc * NH) / 8, 256>>>(qp, kp, ahi, alo);

    // output projection
    gemm_mma<<<gg, 256, SMEM_REQ>>>(ahi, alo, woh, wol, WO_b, out);
}

// round 5
// speedup vs baseline: 3.6518x; 1.3582x over previous
#include <cuda_runtime.h>
#include <cuda_fp16.h>

// ---------------------------------------------------------------------------
// Problem constants
// ---------------------------------------------------------------------------
constexpr int Bc  = 8;
constexpr int Lc  = 4096;
constexpr int NH  = 16;
constexpr int HD  = 64;
constexpr int HID = 1024;
constexpr int MTOK = Bc * Lc;       // 32768
constexpr int Kdim = 1024;
constexpr int NQK  = 2048;          // fused Q|K output width

// GEMM tiling
constexpr int BM = 128, BN = 128, BK = 64;
constexpr int NC = Kdim / BK;       // 16 k-chunks
// stage layout (bytes): Ahi 16K | Bhi 16K | Blo 16K
constexpr int ST_A   = 0;
constexpr int ST_BHI = 16384;
constexpr int ST_BLO = 32768;
constexpr int STAGE_BYTES = 49152;
constexpr int NSLOT = 3;
constexpr int SMEM_REQ = NSLOT * STAGE_BYTES + 1024;

// ---------------------------------------------------------------------------
// Scratch (device globals: no allocation allowed)
// ---------------------------------------------------------------------------
__device__ float g_qk [(size_t)MTOK * NQK];    // fused Q|K output (fp32)
__device__ float g_ak [Bc * HID];
__device__ float g_av [Bc * HID];
__device__ float g_bqk[NQK];                   // concat bias
__device__ __half g_xhi [(size_t)MTOK * HID];
__device__ __half g_ahi [(size_t)MTOK * HID];  // attention out (fp16 hi)
__device__ __half g_wqkT_hi[(size_t)NQK * Kdim], g_wqkT_lo[(size_t)NQK * Kdim];
__device__ __half g_woT_hi [(size_t)Kdim * HID], g_woT_lo [(size_t)Kdim * HID];

// ---------------------------------------------------------------------------
// helpers
// ---------------------------------------------------------------------------
__device__ __forceinline__ unsigned smem_u32(const void* p) {
    unsigned a;
    asm("{ .reg .u64 t; cvta.to.shared.u64 t, %1; cvt.u32.u64 %0, t; }"
        : "=r"(a) : "l"(p));
    return a;
}
__device__ __forceinline__ void cp16(unsigned saddr, const void* g) {
    asm volatile("cp.async.cg.shared.global [%0], [%1], 16;\n"
                 :: "r"(saddr), "l"(g));
}
#define CP_COMMIT() asm volatile("cp.async.commit_group;\n" ::: "memory")
#define CP_WAIT1()  asm volatile("cp.async.wait_group 1;\n" ::: "memory")
#define CP_WAIT0()  asm volatile("cp.async.wait_group 0;\n" ::: "memory")

__device__ __forceinline__ void ldsm4(unsigned& r0, unsigned& r1,
                                      unsigned& r2, unsigned& r3, unsigned a) {
    asm volatile("ldmatrix.sync.aligned.m8n8.x4.shared.b16 {%0,%1,%2,%3}, [%4];"
                 : "=r"(r0), "=r"(r1), "=r"(r2), "=r"(r3) : "r"(a));
}
__device__ __forceinline__ void mma16816(float* c, const unsigned* a,
                                         const unsigned* b) {
    asm volatile(
        "mma.sync.aligned.m16n8k16.row.col.f32.f16.f16.f32 "
        "{%0,%1,%2,%3}, {%4,%5,%6,%7}, {%8,%9}, {%0,%1,%2,%3};"
        : "+f"(c[0]), "+f"(c[1]), "+f"(c[2]), "+f"(c[3])
        : "r"(a[0]), "r"(a[1]), "r"(a[2]), "r"(a[3]), "r"(b[0]), "r"(b[1]));
}

// ---------------------------------------------------------------------------
// 2-pass split-fp16 HMMA GEMM: C[M, N] = Ahi @ (Bhi + Blo)^T + bias
// B operands transposed: [N, K] K-major. CTA 128x128, BK=64, 8 warps,
// warp tile 64x32, 3-slot cp.async pipeline (2 loads in flight, load-before-
// compute, one __syncthreads per chunk).
// ---------------------------------------------------------------------------
__global__ __launch_bounds__(256, 1)
void gemm_mma2(const __half* __restrict__ Ahi,
               const __half* __restrict__ Bhi, const __half* __restrict__ Blo,
               const float* __restrict__ bias, float* __restrict__ C, int ldc)
{
    extern __shared__ char smem_raw[];
    const unsigned sbase = (smem_u32(smem_raw) + 1023u) & ~1023u;
    const int tid  = threadIdx.x;
    const int wid  = tid >> 5;
    const int lane = tid & 31;
    const int row0 = blockIdx.y * BM;
    const int col0 = blockIdx.x * BN;

    auto load_chunk = [&](int c, int slot) {
        const unsigned sa = sbase + slot * STAGE_BYTES;
        const int kt = c * BK;
        #pragma unroll
        for (int i = 0; i < 4; ++i) {
            int v = tid + i * 256;          // 0..1023
            int r = v >> 3, u = v & 7;      // row 0..127, 16B unit 0..7
            unsigned bo = (unsigned)(r * 128 + u * 16);
            unsigned so = bo ^ ((bo >> 3) & 0x70);   // SW128
            size_t goA = (size_t)(row0 + r) * Kdim + kt + u * 8;
            size_t goB = (size_t)(col0 + r) * Kdim + kt + u * 8;
            cp16(sa + ST_A   + so, Ahi + goA);
            cp16(sa + ST_BHI + so, Bhi + goB);
            cp16(sa + ST_BLO + so, Blo + goB);
        }
        CP_COMMIT();
    };

    // per-lane ldmatrix address components
    const int mrow0 = (wid >> 2) * 64;      // warp M offset
    const int nrow0 = (wid & 3) * 32;       // warp N offset
    const unsigned rtA  = (lane & 7) + ((lane >> 3) & 1) * 8;
    const unsigned s16A = ((lane >> 4) & 1) * 16;
    const unsigned rtB  = (lane & 7) + ((lane >> 4) & 1) * 8;
    const unsigned s16B = ((lane >> 3) & 1) * 16;
    const unsigned xorv = (lane & 7) * 16;

    float acc[4][4][4];
    #pragma unroll
    for (int mi = 0; mi < 4; ++mi)
        #pragma unroll
        for (int ni = 0; ni < 4; ++ni)
            #pragma unroll
            for (int r = 0; r < 4; ++r) acc[mi][ni][r] = 0.f;

    load_chunk(0, 0);
    load_chunk(1, 1);

    for (int c = 0; c < NC; ++c) {
        const int slot = c % NSLOT;
        CP_WAIT1();                      // stage c landed
        __syncthreads();                 // all warps done with slot (c+2)%3
        if (c + 2 < NC) load_chunk(c + 2, (c + 2) % NSLOT);

        const unsigned sa   = sbase + slot * STAGE_BYTES;
        const unsigned pA   = sa + ST_A   + (mrow0 + rtA) * 128;
        const unsigned pBhi = sa + ST_BHI + (nrow0 + rtB) * 128;
        const unsigned pBlo = sa + ST_BLO + (nrow0 + rtB) * 128;

        #pragma unroll
        for (int kk = 0; kk < 4; ++kk) {
            const unsigned colA = ((unsigned)(kk * 32) + s16A) ^ xorv;
            const unsigned colB = ((unsigned)(kk * 32) + s16B) ^ xorv;
            unsigned ah[4][4], bh[2][4], bl[2][4];
            #pragma unroll
            for (int mi = 0; mi < 4; ++mi)
                ldsm4(ah[mi][0], ah[mi][1], ah[mi][2], ah[mi][3],
                      pA + mi * 2048 + colA);
            #pragma unroll
            for (int nb = 0; nb < 2; ++nb) {
                ldsm4(bh[nb][0], bh[nb][1], bh[nb][2], bh[nb][3],
                      pBhi + nb * 2048 + colB);
                ldsm4(bl[nb][0], bl[nb][1], bl[nb][2], bl[nb][3],
                      pBlo + nb * 2048 + colB);
            }
            #pragma unroll
            for (int mi = 0; mi < 4; ++mi)
                #pragma unroll
                for (int ni = 0; ni < 4; ++ni) {
                    const unsigned* bhp = &bh[ni >> 1][(ni & 1) * 2];
                    const unsigned* blp = &bl[ni >> 1][(ni & 1) * 2];
                    mma16816(acc[mi][ni], ah[mi], bhp);   // A*Bhi
                    mma16816(acc[mi][ni], ah[mi], blp);   // A*Blo
                }
        }
    }
    CP_WAIT0();

    // epilogue: acc + bias -> C
    #pragma unroll
    for (int ni = 0; ni < 4; ++ni) {
        const int cc = col0 + nrow0 + ni * 8 + (lane & 3) * 2;
        const float b0 = bias[cc], b1 = bias[cc + 1];
        #pragma unroll
        for (int mi = 0; mi < 4; ++mi) {
            const int r = row0 + mrow0 + mi * 16 + (lane >> 2);
            float2 v0 = make_float2(acc[mi][ni][0] + b0, acc[mi][ni][1] + b1);
            float2 v1 = make_float2(acc[mi][ni][2] + b0, acc[mi][ni][3] + b1);
            *(float2*)(C + (size_t)r * ldc + cc)       = v0;
            *(float2*)(C + (size_t)(r + 8) * ldc + cc) = v1;
        }
    }
}

// ---------------------------------------------------------------------------
// fp32 -> fp16 convert (hi only), vectorized
// ---------------------------------------------------------------------------
__global__ __launch_bounds__(256)
void to_half(const float* __restrict__ in, __half* __restrict__ out, int n4)
{
    int i = blockIdx.x * blockDim.x + threadIdx.x;
    if (i >= n4) return;
    float4 v = ((const float4*)in)[i];
    __half2* op = (__half2*)(out + (size_t)i * 4);
    op[0] = __half2(__float2half_rn(v.x), __float2half_rn(v.y));
    op[1] = __half2(__float2half_rn(v.z), __float2half_rn(v.w));
}

// ---------------------------------------------------------------------------
// W [K,N] fp32 -> W^T hi/lo fp16 [N,K]
// ---------------------------------------------------------------------------
__global__ __launch_bounds__(256)
void transpose_split(const float* __restrict__ W,
                     __half* __restrict__ ThT, __half* __restrict__ TlT)
{
    __shared__ float t[32][33];
    const int tx = threadIdx.x, ty = threadIdx.y;   // (32, 8)
    const int n0 = blockIdx.x * 32, k0 = blockIdx.y * 32;
    #pragma unroll
    for (int i = 0; i < 32; i += 8)
        t[ty + i][tx] = W[(size_t)(k0 + ty + i) * HID + n0 + tx];
    __syncthreads();
    #pragma unroll
    for (int i = 0; i < 32; i += 8) {
        float v = t[tx][ty + i];
        __half h = __float2half_rn(v);
        __half l = __float2half_rn(v - __half2float(h));
        ThT[(size_t)(n0 + ty + i) * Kdim + k0 + tx] = h;
        TlT[(size_t)(n0 + ty + i) * Kdim + k0 + tx] = l;
    }
}

// ---------------------------------------------------------------------------
// Tiny projections: ak = ax@WK + bK, av = ax@WV + bV (fp32, 8x1024 each)
// ---------------------------------------------------------------------------
__global__ __launch_bounds__(256)
void proj_small(const float* __restrict__ ax,
                const float* __restrict__ WK, const float* __restrict__ WKb,
                const float* __restrict__ WV, const float* __restrict__ WVb)
{
    __shared__ float xs[HID];
    const int sel = blockIdx.x >> 5;
    const int bb  = (blockIdx.x >> 2) & 7;
    const int n   = ((blockIdx.x & 3) << 8) + threadIdx.x;
    for (int i = threadIdx.x; i < HID; i += 256) xs[i] = ax[bb * HID + i];
    __syncthreads();
    const float* W    = sel ? WV  : WK;
    const float* bias = sel ? WVb : WKb;
    float acc = 0.f;
    #pragma unroll 8
    for (int kk = 0; kk < HID; ++kk)
        acc = fmaf(xs[kk], W[(size_t)kk * HID + n], acc);
    float* o = sel ? g_av : g_ak;
    o[bb * HID + n] = acc + bias[n];
}

// ---------------------------------------------------------------------------
// Attention on fused qk buffer (row stride NQK), emits fp16 output.
// ---------------------------------------------------------------------------
__global__ __launch_bounds__(256)
void attn_kernel(const float* __restrict__ qk, __half* __restrict__ ahi)
{
    const int w    = (blockIdx.x * blockDim.x + threadIdx.x) >> 5;
    const int lane = threadIdx.x & 31;
    const int h = w & 15;
    const int l = (w >> 4) & (Lc - 1);
    const int b = w >> 16;

    const size_t tok   = (size_t)(b * Lc + l);
    const size_t qbase = tok * NQK + h * HD + lane * 2;          // q cols
    const size_t kbase = qbase + HID;                            // k cols
    const size_t obase = tok * HID + h * HD + lane * 2;
    const size_t gbase = (size_t)b * HID + h * HD + lane * 2;

    float2 qv = *(const float2*)(qk + qbase);
    float2 k0 = *(const float2*)(g_ak + gbase);
    float2 v0 = *(const float2*)(g_av + gbase);
    float2 k1 = make_float2(0.f, 0.f);
    float2 k3 = make_float2(0.f, 0.f);
    if (l > 0)      k1 = *(const float2*)(qk + kbase - NQK);
    float2 k2 = *(const float2*)(qk + kbase);
    if (l < Lc - 1) k3 = *(const float2*)(qk + kbase + NQK);

    float p0 = qv.x * k0.x + qv.y * k0.y;
    float p1 = qv.x * k1.x + qv.y * k1.y;
    float p2 = qv.x * k2.x + qv.y * k2.y;
    float p3 = qv.x * k3.x + qv.y * k3.y;
    #pragma unroll
    for (int o = 16; o; o >>= 1) {
        p0 += __shfl_xor_sync(0xFFFFFFFFu, p0, o);
        p1 += __shfl_xor_sync(0xFFFFFFFFu, p1, o);
        p2 += __shfl_xor_sync(0xFFFFFFFFu, p2, o);
        p3 += __shfl_xor_sync(0xFFFFFFFFu, p3, o);
    }
    const float scale = 0.125f;
    float s0 = p0 * scale, s1 = p1 * scale, s2 = p2 * scale, s3 = p3 * scale;
    float m = fmaxf(fmaxf(s0, s1), fmaxf(s2, s3));
    float e0 = __expf(s0 - m), e1 = __expf(s1 - m),
          e2 = __expf(s2 - m), e3 = __expf(s3 - m);
    float inv = 1.f / (e0 + e1 + e2 + e3);
    float a0 = e0 * inv, a1 = e1 * inv, a2 = e2 * inv, a3 = e3 * inv;

    float ox = a0 * v0.x + a1 * k1.x + a2 * k2.x + a3 * k3.x;
    float oy = a0 * v0.y + a1 * k1.y + a2 * k2.y + a3 * k3.y;

    *(__half2*)(ahi + obase) = __half2(__float2half_rn(ox), __float2half_rn(oy));
}

// ---------------------------------------------------------------------------
extern "C" void kernel_launch(void* const* d_in, const int* in_sizes, int n_in,
                              void* d_out, int out_size)
{
    const float* x    = (const float*)d_in[0];
    const float* ax   = (const float*)d_in[1];
    const float* WQ_w = (const float*)d_in[2];
    const float* WQ_b = (const float*)d_in[3];
    const float* WK_w = (const float*)d_in[4];
    const float* WK_b = (const float*)d_in[5];
    const float* WV_w = (const float*)d_in[6];
    const float* WV_b = (const float*)d_in[7];
    const float* WO_w = (const float*)d_in[8];
    const float* WO_b = (const float*)d_in[9];
    float* out = (float*)d_out;

    float *qkp, *bqk;
    __half *xhi, *ahi, *wqkh, *wqkl, *woh, *wol;
    cudaGetSymbolAddress((void**)&qkp,  g_qk);
    cudaGetSymbolAddress((void**)&bqk,  g_bqk);
    cudaGetSymbolAddress((void**)&xhi,  g_xhi);
    cudaGetSymbolAddress((void**)&ahi,  g_ahi);
    cudaGetSymbolAddress((void**)&wqkh, g_wqkT_hi);
    cudaGetSymbolAddress((void**)&wqkl, g_wqkT_lo);
    cudaGetSymbolAddress((void**)&woh,  g_woT_hi);
    cudaGetSymbolAddress((void**)&wol,  g_woT_lo);

    cudaFuncSetAttribute(gemm_mma2,
                         cudaFuncAttributeMaxDynamicSharedMemorySize, SMEM_REQ);

    // conversions
    const int n4 = MTOK * HID / 4;
    to_half<<<n4 / 256, 256>>>(x, xhi, n4);
    dim3 tb(32, 8), tg(32, 32);
    transpose_split<<<tg, tb>>>(WQ_w, wqkh, wqkl);                     // rows 0..1023
    transpose_split<<<tg, tb>>>(WK_w, wqkh + (size_t)HID * Kdim,
                                      wqkl + (size_t)HID * Kdim);      // rows 1024..2047
    transpose_split<<<tg, tb>>>(WO_w, woh, wol);
    cudaMemcpyAsync(bqk,       WQ_b, HID * sizeof(float), cudaMemcpyDeviceToDevice);
    cudaMemcpyAsync(bqk + HID, WK_b, HID * sizeof(float), cudaMemcpyDeviceToDevice);
    proj_small<<<64, 256>>>(ax, WK_w, WK_b, WV_w, WV_b);

    // fused Q|K projection: [MTOK, 2048]
    dim3 gqk(NQK / BN, MTOK / BM);   // (16, 256)
    gemm_mma2<<<gqk, 256, SMEM_REQ>>>(xhi, wqkh, wqkl, bqk, qkp, NQK);

    // attention -> fp16 output
    attn_kernel<<<(Bc * Lc * NH) / 8, 256>>>(qkp, ahi);

    // output projection
    dim3 go(HID / BN, MTOK / BM);    // (8, 256)
    gemm_mma2<<<go, 256, SMEM_REQ>>>(ahi, woh, wol, WO_b, out, HID);
}